// round 2
// baseline (speedup 1.0000x reference)
#include <cuda_runtime.h>
#include <cstdint>
#include <math.h>

#define L_SEQ 2048
#define B_SZ  16
#define H_DIM 512
#define NST   32

// ---------------- device scratch (static allocation is allowed) ----------------
__device__ float4 g_zc[H_DIM * NST];                    // zr, zi, 2*Cm_r, 2*Cm_i
__device__ float  g_mu[L_SEQ * B_SZ];
__device__ float  g_rstd[L_SEQ * B_SZ];
__device__ float  g_Wp[1024 * 512];                     // permuted + tf32-rounded W
__device__ float  g_gelu[(size_t)B_SZ * H_DIM * L_SEQ]; // gelu(y), tf32-rounded, (B,H,L)

// ---------------- helpers ----------------
__device__ __forceinline__ float tf32r(float x) {
    unsigned r;
    asm("cvt.rna.tf32.f32 %0, %1;" : "=r"(r) : "f"(x));
    return __uint_as_float(r);
}

__device__ __forceinline__ void mma_tf32(float* d, const unsigned* a, const unsigned* b) {
    asm volatile(
        "mma.sync.aligned.m16n8k8.row.col.f32.tf32.tf32.f32 "
        "{%0,%1,%2,%3}, {%4,%5,%6,%7}, {%8,%9}, {%0,%1,%2,%3};\n"
        : "+f"(d[0]), "+f"(d[1]), "+f"(d[2]), "+f"(d[3])
        : "r"(a[0]), "r"(a[1]), "r"(a[2]), "r"(a[3]), "r"(b[0]), "r"(b[1]));
}

// ---------------- K0: per-(h,n) SSM parameters ----------------
__global__ void k_params(const float* __restrict__ log_dt, const float* __restrict__ C,
                         const float* __restrict__ logAr, const float* __restrict__ Aim) {
    int i = blockIdx.x * 256 + threadIdx.x;      // h*32 + n
    if (i >= H_DIM * NST) return;
    int h = i >> 5;
    float dt = expf(log_dt[h]);
    float ar = -expf(logAr[i]);
    float ai = Aim[i];
    float dr = ar * dt, di = ai * dt;
    float e = expf(dr);
    float sn, cs;
    sincosf(di, &sn, &cs);
    float zr = e * cs, zi = e * sn;              // z = exp(dt*A)
    float wr = zr - 1.0f, wi = zi;               // z - 1
    float den = 1.0f / (ar * ar + ai * ai);
    float war = (wr * ar + wi * ai) * den;       // (z-1)/A
    float wai = (wi * ar - wr * ai) * den;
    float ccr = C[2 * i], cci = C[2 * i + 1];
    float cmr = ccr * war - cci * wai;           // Cm = C*(z-1)/A
    float cmi = ccr * wai + cci * war;
    g_zc[i] = make_float4(zr, zi, 2.0f * cmr, 2.0f * cmi);
}

// ---------------- K0b: permute W rows so (a,gate) pairs share an m16 tile ----------------
// Wp[16T + j]     = W[8T + j]          (a-rows,   local rows 0..7)
// Wp[16T + 8 + j] = W[512 + 8T + j]    (g-rows,   local rows 8..15)
__global__ void k_wperm(const float* __restrict__ W) {
    int idx = blockIdx.x * 256 + threadIdx.x;    // 0 .. 1024*512-1
    if (idx >= 1024 * 512) return;
    int r = idx >> 9, k = idx & 511;
    int T = r >> 4, j8 = r & 15;
    int src = (j8 < 8) ? (8 * T + j8) : (512 + 8 * T + (j8 - 8));
    g_Wp[idx] = tf32r(W[src * 512 + k]);
}

// ---------------- K1: LayerNorm stats per (l,b) ----------------
__global__ void k_lnstats(const float* __restrict__ u) {
    int row = blockIdx.x * 8 + (threadIdx.x >> 5);   // l*B + b
    int lane = threadIdx.x & 31;
    const float4* p = (const float4*)(u + (size_t)row * H_DIM);
    float s = 0.f, ss = 0.f;
#pragma unroll
    for (int j = 0; j < 4; ++j) {
        float4 v = p[lane + 32 * j];
        s  += v.x + v.y + v.z + v.w;
        ss += v.x * v.x + v.y * v.y + v.z * v.z + v.w * v.w;
    }
#pragma unroll
    for (int o = 16; o; o >>= 1) {
        s  += __shfl_xor_sync(0xffffffffu, s, o);
        ss += __shfl_xor_sync(0xffffffffu, ss, o);
    }
    if (lane == 0) {
        float mu = s * (1.0f / 512.0f);
        g_mu[row] = mu;
        g_rstd[row] = rsqrtf(fmaf(ss, 1.0f / 512.0f, -mu * mu) + 1e-5f);
    }
}

// ---------------- K3: fused LN-apply + diagonal-SSM scan + D-skip + GELU ----------------
// warp = (b, h); lane = state n.  Block: 16 warps = 16 consecutive h for one b.
__global__ void __launch_bounds__(512, 1) k_scan(const float* __restrict__ u,
                                                 const float* __restrict__ Dvec,
                                                 const float* __restrict__ lnw,
                                                 const float* __restrict__ lnb) {
    __shared__ float un_sm[32][17];        // [l-in-chunk][h-local]
    __shared__ float red_sm[16][32][9];    // [warp][l-in-chunk][partial 0..7]
    const int b  = blockIdx.y;
    const int h0 = blockIdx.x * 16;
    const int tid = threadIdx.x;
    const int w = tid >> 5, lane = tid & 31;
    const int h = h0 + w;

    float4 zc = g_zc[h * NST + lane];
    const float zr = zc.x, zi = zc.y, cr = zc.z, ci = zc.w;
    const float Dh = Dvec[h];

    const int li = tid >> 4;               // staging role: l within chunk (0..31)
    const int lj = tid & 15;               // staging role: h local (0..15)
    const float wj = lnw[h0 + lj], bj = lnb[h0 + lj];

    float sr = 0.f, si = 0.f;
    const float* ub = u + (size_t)b * H_DIM;
    float* gout = g_gelu + ((size_t)(b * H_DIM + h)) * L_SEQ;

#pragma unroll 1
    for (int c = 0; c < L_SEQ / 32; ++c) {
        const int l0 = c * 32;
        // stage 32 x 16 LayerNorm'd inputs
        {
            int lg = l0 + li;
            float uv = ub[(size_t)lg * (B_SZ * H_DIM) + h0 + lj];
            int sidx = lg * B_SZ + b;
            un_sm[li][lj] = (uv - g_mu[sidx]) * g_rstd[sidx] * wj + bj;
        }
        __syncthreads();
#pragma unroll
        for (int t = 0; t < 32; ++t) {
            float ul = un_sm[t][w];
            float nsr = fmaf(zr, sr, fmaf(-zi, si, ul));
            float nsi = fmaf(zr, si, zi * sr);
            sr = nsr; si = nsi;
            float p = fmaf(cr, sr, -(ci * si));
            p += __shfl_xor_sync(0xffffffffu, p, 16);
            p += __shfl_xor_sync(0xffffffffu, p, 8);
            if (lane < 8) red_sm[w][t][lane] = p;
        }
        __syncwarp();
        float acc = 0.f;
#pragma unroll
        for (int j = 0; j < 8; ++j) acc += red_sm[w][lane][j];
        float y = acc + Dh * un_sm[lane][w];                     // + D-skip (uses un)
        float gv = 0.5f * y * (1.0f + erff(y * 0.70710678118654752f)); // exact GELU
        gout[l0 + lane] = tf32r(gv);
        __syncthreads();
    }
}

// ---------------- K4: tf32 GEMM (Wp @ gelu) + bias + GLU + residual + transpose ----------------
struct GemmBufs { float A[2][16][132]; float Bm[2][16][132]; };
union  GemmSmem { GemmBufs gb; float outsm[128][68]; };

__global__ void __launch_bounds__(256, 1) k_gemm(const float* __restrict__ u,
                                                 const float* __restrict__ bconv,
                                                 float* __restrict__ out) {
    __shared__ GemmSmem sm;
    const int n0 = blockIdx.x * 128;       // l tile
    const int m0 = blockIdx.y * 128;       // Wp row tile
    const int h0 = blockIdx.y * 64;        // output h tile
    const int b  = blockIdx.z;
    const int tid = threadIdx.x;
    const int warp = tid >> 5, lane = tid & 31;
    const int wm = warp >> 2, wn = warp & 3;
    const int tig = lane & 3, gq = lane >> 2;

    float acc[4][4][4];
#pragma unroll
    for (int a = 0; a < 4; ++a)
#pragma unroll
        for (int bq = 0; bq < 4; ++bq)
#pragma unroll
            for (int cc = 0; cc < 4; ++cc) acc[a][bq][cc] = 0.f;

    const float* Aglob = g_Wp + (size_t)m0 * 512;
    const float* Bglob = g_gelu + ((size_t)b * H_DIM) * L_SEQ + n0;

    // prologue: tile 0
#pragma unroll
    for (int i = 0; i < 2; ++i) {
        int idx = tid + 256 * i;
        int row = idx >> 2, kk4 = idx & 3;
        float4 v = *(const float4*)(Aglob + (size_t)row * 512 + kk4 * 4);
        sm.gb.A[0][kk4 * 4 + 0][row] = v.x;
        sm.gb.A[0][kk4 * 4 + 1][row] = v.y;
        sm.gb.A[0][kk4 * 4 + 2][row] = v.z;
        sm.gb.A[0][kk4 * 4 + 3][row] = v.w;
        int krow = idx >> 5, col4 = idx & 31;
        float4 wv = *(const float4*)(Bglob + (size_t)krow * L_SEQ + col4 * 4);
        *(float4*)&sm.gb.Bm[0][krow][col4 * 4] = wv;
    }
    __syncthreads();

    float4 ra[2], rb[2];
#pragma unroll 1
    for (int kt = 0; kt < 32; ++kt) {
        const int buf = kt & 1;
        if (kt < 31) {
            int k0 = (kt + 1) * 16;
#pragma unroll
            for (int i = 0; i < 2; ++i) {
                int idx = tid + 256 * i;
                int row = idx >> 2, kk4 = idx & 3;
                ra[i] = *(const float4*)(Aglob + (size_t)row * 512 + k0 + kk4 * 4);
                int krow = idx >> 5, col4 = idx & 31;
                rb[i] = *(const float4*)(Bglob + (size_t)(k0 + krow) * L_SEQ + col4 * 4);
            }
        }
#pragma unroll
        for (int kk = 0; kk < 16; kk += 8) {
            unsigned af[4][4], bf[4][2];
#pragma unroll
            for (int mm = 0; mm < 4; ++mm) {
                int mr = wm * 64 + mm * 16;
                af[mm][0] = __float_as_uint(sm.gb.A[buf][kk + tig    ][mr + gq]);
                af[mm][1] = __float_as_uint(sm.gb.A[buf][kk + tig    ][mr + gq + 8]);
                af[mm][2] = __float_as_uint(sm.gb.A[buf][kk + tig + 4][mr + gq]);
                af[mm][3] = __float_as_uint(sm.gb.A[buf][kk + tig + 4][mr + gq + 8]);
            }
#pragma unroll
            for (int nn = 0; nn < 4; ++nn) {
                int nc = wn * 32 + nn * 8;
                bf[nn][0] = __float_as_uint(sm.gb.Bm[buf][kk + tig    ][nc + gq]);
                bf[nn][1] = __float_as_uint(sm.gb.Bm[buf][kk + tig + 4][nc + gq]);
            }
#pragma unroll
            for (int mm = 0; mm < 4; ++mm)
#pragma unroll
                for (int nn = 0; nn < 4; ++nn)
                    mma_tf32(acc[mm][nn], af[mm], bf[nn]);
        }
        if (kt < 31) {
            const int nb = buf ^ 1;
#pragma unroll
            for (int i = 0; i < 2; ++i) {
                int idx = tid + 256 * i;
                int row = idx >> 2, kk4 = idx & 3;
                sm.gb.A[nb][kk4 * 4 + 0][row] = ra[i].x;
                sm.gb.A[nb][kk4 * 4 + 1][row] = ra[i].y;
                sm.gb.A[nb][kk4 * 4 + 2][row] = ra[i].z;
                sm.gb.A[nb][kk4 * 4 + 3][row] = ra[i].w;
                int krow = idx >> 5, col4 = idx & 31;
                *(float4*)&sm.gb.Bm[nb][krow][col4 * 4] = rb[i];
            }
        }
        __syncthreads();
    }

    // epilogue: bias + GLU in-register (a at row g, gate at row g+8 of each m16 tile)
#pragma unroll
    for (int mm = 0; mm < 4; ++mm) {
        int hl = wm * 32 + mm * 8 + gq;
        float ba = bconv[h0 + hl];
        float bg = bconv[512 + h0 + hl];
#pragma unroll
        for (int nn = 0; nn < 4; ++nn) {
            int col = wn * 32 + nn * 8 + 2 * tig;
#pragma unroll
            for (int cc = 0; cc < 2; ++cc) {
                float av = acc[mm][nn][cc] + ba;
                float gv = acc[mm][nn][2 + cc] + bg;
                sm.outsm[col + cc][hl] = av / (1.0f + expf(-gv));   // a * sigmoid(g)
            }
        }
    }
    __syncthreads();

    // residual add + coalesced (L,B,H) store
#pragma unroll
    for (int i = 0; i < 8; ++i) {
        int idx = tid + 256 * i;
        int hq = idx & 15, ll = idx >> 4;
        size_t gaddr = (size_t)(n0 + ll) * (B_SZ * H_DIM) + (size_t)b * H_DIM + h0 + hq * 4;
        float4 uv = *(const float4*)(u + gaddr);
        float4 r = *(const float4*)&sm.outsm[ll][hq * 4];
        r.x += uv.x; r.y += uv.y; r.z += uv.z; r.w += uv.w;
        *(float4*)(out + gaddr) = r;
    }
}

// ---------------- launch ----------------
extern "C" void kernel_launch(void* const* d_in, const int* in_sizes, int n_in,
                              void* d_out, int out_size) {
    const float* u      = (const float*)d_in[0];
    const float* log_dt = (const float*)d_in[1];
    const float* C      = (const float*)d_in[2];
    const float* logAr  = (const float*)d_in[3];
    const float* Aim    = (const float*)d_in[4];
    const float* Dv     = (const float*)d_in[5];
    const float* W      = (const float*)d_in[6];
    const float* bconv  = (const float*)d_in[7];
    const float* lnw    = (const float*)d_in[8];
    const float* lnb    = (const float*)d_in[9];
    float* out = (float*)d_out;
    (void)in_sizes; (void)n_in; (void)out_size;

    k_params <<<64,   256>>>(log_dt, C, logAr, Aim);
    k_wperm  <<<2048, 256>>>(W);
    k_lnstats<<<4096, 256>>>(u);
    k_scan   <<<dim3(32, 16), 512>>>(u, Dv, lnw, lnb);
    k_gemm   <<<dim3(16, 8, 16), 256>>>(u, bconv, out);
}

// round 3
// speedup vs baseline: 1.0007x; 1.0007x over previous
#include <cuda_runtime.h>
#include <cstdint>
#include <math.h>

#define L_SEQ 2048
#define B_SZ  16
#define H_DIM 512
#define NST   32

// ---------------- device scratch (static allocation is allowed) ----------------
__device__ float4 g_zc[H_DIM * NST];                    // zr, zi, 2*Cm_r, 2*Cm_i
__device__ float  g_mu[L_SEQ * B_SZ];
__device__ float  g_rstd[L_SEQ * B_SZ];
__device__ float  g_Wp[1024 * 512];                     // permuted + tf32-rounded W
__device__ float  g_gelu[(size_t)B_SZ * H_DIM * L_SEQ]; // gelu(y), tf32-rounded, (B,H,L)

// ---------------- helpers ----------------
__device__ __forceinline__ float tf32r(float x) {
    unsigned r;
    asm("cvt.rna.tf32.f32 %0, %1;" : "=r"(r) : "f"(x));
    return __uint_as_float(r);
}

__device__ __forceinline__ void mma_tf32(float* d, const unsigned* a, const unsigned* b) {
    asm volatile(
        "mma.sync.aligned.m16n8k8.row.col.f32.tf32.tf32.f32 "
        "{%0,%1,%2,%3}, {%4,%5,%6,%7}, {%8,%9}, {%0,%1,%2,%3};\n"
        : "+f"(d[0]), "+f"(d[1]), "+f"(d[2]), "+f"(d[3])
        : "r"(a[0]), "r"(a[1]), "r"(a[2]), "r"(a[3]), "r"(b[0]), "r"(b[1]));
}

// ---------------- K0: per-(h,n) SSM parameters ----------------
__global__ void k_params(const float* __restrict__ log_dt, const float* __restrict__ C,
                         const float* __restrict__ logAr, const float* __restrict__ Aim) {
    int i = blockIdx.x * 256 + threadIdx.x;      // h*32 + n
    if (i >= H_DIM * NST) return;
    int h = i >> 5;
    float dt = expf(log_dt[h]);
    float ar = -expf(logAr[i]);
    float ai = Aim[i];
    float dr = ar * dt, di = ai * dt;
    float e = expf(dr);
    float sn, cs;
    sincosf(di, &sn, &cs);
    float zr = e * cs, zi = e * sn;              // z = exp(dt*A)
    float wr = zr - 1.0f, wi = zi;               // z - 1
    float den = 1.0f / (ar * ar + ai * ai);
    float war = (wr * ar + wi * ai) * den;       // (z-1)/A
    float wai = (wi * ar - wr * ai) * den;
    float ccr = C[2 * i], cci = C[2 * i + 1];
    float cmr = ccr * war - cci * wai;           // Cm = C*(z-1)/A
    float cmi = ccr * wai + cci * war;
    g_zc[i] = make_float4(zr, zi, 2.0f * cmr, 2.0f * cmi);
}

// ---------------- K0b: permute W rows so (a,gate) pairs share an m16 tile ----------------
// Wp[16T + j]     = W[8T + j]          (a-rows,   local rows 0..7)
// Wp[16T + 8 + j] = W[512 + 8T + j]    (g-rows,   local rows 8..15)
__global__ void k_wperm(const float* __restrict__ W) {
    int idx = blockIdx.x * 256 + threadIdx.x;    // 0 .. 1024*512-1
    if (idx >= 1024 * 512) return;
    int r = idx >> 9, k = idx & 511;
    int T = r >> 4, j8 = r & 15;
    int src = (j8 < 8) ? (8 * T + j8) : (512 + 8 * T + (j8 - 8));
    g_Wp[idx] = tf32r(W[src * 512 + k]);
}

// ---------------- K1: LayerNorm stats per (l,b) ----------------
__global__ void k_lnstats(const float* __restrict__ u) {
    int row = blockIdx.x * 8 + (threadIdx.x >> 5);   // l*B + b
    int lane = threadIdx.x & 31;
    const float4* p = (const float4*)(u + (size_t)row * H_DIM);
    float s = 0.f, ss = 0.f;
#pragma unroll
    for (int j = 0; j < 4; ++j) {
        float4 v = p[lane + 32 * j];
        s  += v.x + v.y + v.z + v.w;
        ss += v.x * v.x + v.y * v.y + v.z * v.z + v.w * v.w;
    }
#pragma unroll
    for (int o = 16; o; o >>= 1) {
        s  += __shfl_xor_sync(0xffffffffu, s, o);
        ss += __shfl_xor_sync(0xffffffffu, ss, o);
    }
    if (lane == 0) {
        float mu = s * (1.0f / 512.0f);
        g_mu[row] = mu;
        g_rstd[row] = rsqrtf(fmaf(ss, 1.0f / 512.0f, -mu * mu) + 1e-5f);
    }
}

// ---------------- K3: fused LN-apply + diagonal-SSM scan + D-skip + GELU ----------------
// warp = (b, h); lane = state n.  Block: 16 warps = 16 consecutive h for one b.
__global__ void __launch_bounds__(512, 1) k_scan(const float* __restrict__ u,
                                                 const float* __restrict__ Dvec,
                                                 const float* __restrict__ lnw,
                                                 const float* __restrict__ lnb) {
    __shared__ float un_sm[32][17];        // [l-in-chunk][h-local]
    __shared__ float red_sm[16][32][9];    // [warp][l-in-chunk][partial 0..7]
    const int b  = blockIdx.y;
    const int h0 = blockIdx.x * 16;
    const int tid = threadIdx.x;
    const int w = tid >> 5, lane = tid & 31;
    const int h = h0 + w;

    float4 zc = g_zc[h * NST + lane];
    const float zr = zc.x, zi = zc.y, cr = zc.z, ci = zc.w;
    const float Dh = Dvec[h];

    const int li = tid >> 4;               // staging role: l within chunk (0..31)
    const int lj = tid & 15;               // staging role: h local (0..15)
    const float wj = lnw[h0 + lj], bj = lnb[h0 + lj];

    float sr = 0.f, si = 0.f;
    const float* ub = u + (size_t)b * H_DIM;
    float* gout = g_gelu + ((size_t)(b * H_DIM + h)) * L_SEQ;

#pragma unroll 1
    for (int c = 0; c < L_SEQ / 32; ++c) {
        const int l0 = c * 32;
        // stage 32 x 16 LayerNorm'd inputs
        {
            int lg = l0 + li;
            float uv = ub[(size_t)lg * (B_SZ * H_DIM) + h0 + lj];
            int sidx = lg * B_SZ + b;
            un_sm[li][lj] = (uv - g_mu[sidx]) * g_rstd[sidx] * wj + bj;
        }
        __syncthreads();
#pragma unroll
        for (int t = 0; t < 32; ++t) {
            float ul = un_sm[t][w];
            float nsr = fmaf(zr, sr, fmaf(-zi, si, ul));
            float nsi = fmaf(zr, si, zi * sr);
            sr = nsr; si = nsi;
            float p = fmaf(cr, sr, -(ci * si));
            p += __shfl_xor_sync(0xffffffffu, p, 16);
            p += __shfl_xor_sync(0xffffffffu, p, 8);
            if (lane < 8) red_sm[w][t][lane] = p;
        }
        __syncwarp();
        float acc = 0.f;
#pragma unroll
        for (int j = 0; j < 8; ++j) acc += red_sm[w][lane][j];
        float y = acc + Dh * un_sm[lane][w];                     // + D-skip (uses un)
        float gv = 0.5f * y * (1.0f + erff(y * 0.70710678118654752f)); // exact GELU
        gout[l0 + lane] = tf32r(gv);
        __syncthreads();
    }
}

// ---------------- K4: tf32 GEMM (Wp @ gelu) + bias + GLU + residual + transpose ----------------
struct GemmBufs { float A[2][16][132]; float Bm[2][16][132]; };
union  GemmSmem { GemmBufs gb; float outsm[128][68]; };

__global__ void __launch_bounds__(256, 1) k_gemm(const float* __restrict__ u,
                                                 const float* __restrict__ bconv,
                                                 float* __restrict__ out) {
    __shared__ GemmSmem sm;
    const int n0 = blockIdx.x * 128;       // l tile
    const int m0 = blockIdx.y * 128;       // Wp row tile
    const int h0 = blockIdx.y * 64;        // output h tile
    const int b  = blockIdx.z;
    const int tid = threadIdx.x;
    const int warp = tid >> 5, lane = tid & 31;
    const int wm = warp >> 2, wn = warp & 3;
    const int tig = lane & 3, gq = lane >> 2;

    float acc[4][4][4];
#pragma unroll
    for (int a = 0; a < 4; ++a)
#pragma unroll
        for (int bq = 0; bq < 4; ++bq)
#pragma unroll
            for (int cc = 0; cc < 4; ++cc) acc[a][bq][cc] = 0.f;

    const float* Aglob = g_Wp + (size_t)m0 * 512;
    const float* Bglob = g_gelu + ((size_t)b * H_DIM) * L_SEQ + n0;

    // prologue: tile 0
#pragma unroll
    for (int i = 0; i < 2; ++i) {
        int idx = tid + 256 * i;
        int row = idx >> 2, kk4 = idx & 3;
        float4 v = *(const float4*)(Aglob + (size_t)row * 512 + kk4 * 4);
        sm.gb.A[0][kk4 * 4 + 0][row] = v.x;
        sm.gb.A[0][kk4 * 4 + 1][row] = v.y;
        sm.gb.A[0][kk4 * 4 + 2][row] = v.z;
        sm.gb.A[0][kk4 * 4 + 3][row] = v.w;
        int krow = idx >> 5, col4 = idx & 31;
        float4 wv = *(const float4*)(Bglob + (size_t)krow * L_SEQ + col4 * 4);
        *(float4*)&sm.gb.Bm[0][krow][col4 * 4] = wv;
    }
    __syncthreads();

    float4 ra[2], rb[2];
#pragma unroll 1
    for (int kt = 0; kt < 32; ++kt) {
        const int buf = kt & 1;
        if (kt < 31) {
            int k0 = (kt + 1) * 16;
#pragma unroll
            for (int i = 0; i < 2; ++i) {
                int idx = tid + 256 * i;
                int row = idx >> 2, kk4 = idx & 3;
                ra[i] = *(const float4*)(Aglob + (size_t)row * 512 + k0 + kk4 * 4);
                int krow = idx >> 5, col4 = idx & 31;
                rb[i] = *(const float4*)(Bglob + (size_t)(k0 + krow) * L_SEQ + col4 * 4);
            }
        }
#pragma unroll
        for (int kk = 0; kk < 16; kk += 8) {
            unsigned af[4][4], bf[4][2];
#pragma unroll
            for (int mm = 0; mm < 4; ++mm) {
                int mr = wm * 64 + mm * 16;
                af[mm][0] = __float_as_uint(sm.gb.A[buf][kk + tig    ][mr + gq]);
                af[mm][1] = __float_as_uint(sm.gb.A[buf][kk + tig    ][mr + gq + 8]);
                af[mm][2] = __float_as_uint(sm.gb.A[buf][kk + tig + 4][mr + gq]);
                af[mm][3] = __float_as_uint(sm.gb.A[buf][kk + tig + 4][mr + gq + 8]);
            }
#pragma unroll
            for (int nn = 0; nn < 4; ++nn) {
                int nc = wn * 32 + nn * 8;
                bf[nn][0] = __float_as_uint(sm.gb.Bm[buf][kk + tig    ][nc + gq]);
                bf[nn][1] = __float_as_uint(sm.gb.Bm[buf][kk + tig + 4][nc + gq]);
            }
#pragma unroll
            for (int mm = 0; mm < 4; ++mm)
#pragma unroll
                for (int nn = 0; nn < 4; ++nn)
                    mma_tf32(acc[mm][nn], af[mm], bf[nn]);
        }
        if (kt < 31) {
            const int nb = buf ^ 1;
#pragma unroll
            for (int i = 0; i < 2; ++i) {
                int idx = tid + 256 * i;
                int row = idx >> 2, kk4 = idx & 3;
                sm.gb.A[nb][kk4 * 4 + 0][row] = ra[i].x;
                sm.gb.A[nb][kk4 * 4 + 1][row] = ra[i].y;
                sm.gb.A[nb][kk4 * 4 + 2][row] = ra[i].z;
                sm.gb.A[nb][kk4 * 4 + 3][row] = ra[i].w;
                int krow = idx >> 5, col4 = idx & 31;
                *(float4*)&sm.gb.Bm[nb][krow][col4 * 4] = rb[i];
            }
        }
        __syncthreads();
    }

    // epilogue: bias + GLU in-register (a at row g, gate at row g+8 of each m16 tile)
#pragma unroll
    for (int mm = 0; mm < 4; ++mm) {
        int hl = wm * 32 + mm * 8 + gq;
        float ba = bconv[h0 + hl];
        float bg = bconv[512 + h0 + hl];
#pragma unroll
        for (int nn = 0; nn < 4; ++nn) {
            int col = wn * 32 + nn * 8 + 2 * tig;
#pragma unroll
            for (int cc = 0; cc < 2; ++cc) {
                float av = acc[mm][nn][cc] + ba;
                float gv = acc[mm][nn][2 + cc] + bg;
                sm.outsm[col + cc][hl] = av / (1.0f + expf(-gv));   // a * sigmoid(g)
            }
        }
    }
    __syncthreads();

    // residual add + coalesced (L,B,H) store
#pragma unroll
    for (int i = 0; i < 8; ++i) {
        int idx = tid + 256 * i;
        int hq = idx & 15, ll = idx >> 4;
        size_t gaddr = (size_t)(n0 + ll) * (B_SZ * H_DIM) + (size_t)b * H_DIM + h0 + hq * 4;
        float4 uv = *(const float4*)(u + gaddr);
        float4 r = *(const float4*)&sm.outsm[ll][hq * 4];
        r.x += uv.x; r.y += uv.y; r.z += uv.z; r.w += uv.w;
        *(float4*)(out + gaddr) = r;
    }
}

// ---------------- launch ----------------
extern "C" void kernel_launch(void* const* d_in, const int* in_sizes, int n_in,
                              void* d_out, int out_size) {
    const float* u      = (const float*)d_in[0];
    const float* log_dt = (const float*)d_in[1];
    const float* C      = (const float*)d_in[2];
    const float* logAr  = (const float*)d_in[3];
    const float* Aim    = (const float*)d_in[4];
    const float* Dv     = (const float*)d_in[5];
    const float* W      = (const float*)d_in[6];
    const float* bconv  = (const float*)d_in[7];
    const float* lnw    = (const float*)d_in[8];
    const float* lnb    = (const float*)d_in[9];
    float* out = (float*)d_out;
    (void)in_sizes; (void)n_in; (void)out_size;

    k_params <<<64,   256>>>(log_dt, C, logAr, Aim);
    k_wperm  <<<2048, 256>>>(W);
    k_lnstats<<<4096, 256>>>(u);
    k_scan   <<<dim3(32, 16), 512>>>(u, Dv, lnw, lnb);
    k_gemm   <<<dim3(16, 8, 16), 256>>>(u, bconv, out);
}